// round 16
// baseline (speedup 1.0000x reference)
#include <cuda_runtime.h>
#include <cuda_bf16.h>
#include <cuda_fp16.h>

// emb[b,f,e] = b2[f,e] + sum_h W2[f,e,h]*relu(x[b,f]*W1[f,h]+b1[f,h])
// Piecewise-linear-in-x: per f, 65 segments; emb = A(seg)*x + C(seg).
// R16: SINGLE fused kernel. Each block (2 features x 1024 rows) builds its
// own fp16 segment tables in smem (redundant per y-block, parallel across
// SMs), then runs the R13 eval loop. No global table traffic, one launch.

#define BN 16384
#define FN 128
#define HN 64
#define EN 16
#define THR_S 72        // threshold stride
#define TAB_S 524       // smem table stride in h4 units
#define ROWS_PER_BLOCK 1024
#define BATCHES 8       // per warp: 128 rows = 8 batches of 16

struct __align__(8) h4 { __half2 a, c; };

// ---------------------------------------------------------------------------
// Branch-free count of { thr[t] <= xs } over 64 sorted entries (7 LDS).
// ---------------------------------------------------------------------------
__device__ __forceinline__ int seg_search(const float* __restrict__ thrp, float xs)
{
    int p = (thrp[31] <= xs) ? 32 : 0;
    p += (thrp[p + 15] <= xs) ? 16 : 0;
    p += (thrp[p + 7]  <= xs) ? 8  : 0;
    p += (thrp[p + 3]  <= xs) ? 4  : 0;
    p += (thrp[p + 1]  <= xs) ? 2  : 0;
    p += (thrp[p]      <= xs) ? 1  : 0;
    return p + ((thrp[p] <= xs) ? 1 : 0);   // in [0,64]
}

// ---------------------------------------------------------------------------
// Fused kernel. Block = 2 features ("pair") x 1024 rows, 256 threads,
// grid (64,16) = 1024 blocks (~1 wave at 7/SM).
// Prologue (per block): threads split 128/feature; stage W2 row, rank-sort
//   hinge thresholds, scan-parallel segment walk (R14) writing fp16 A/C
//   DIRECTLY into the smem table via 2-byte stores.
// Main loop: R13 exact (best measured eval inner loop).
// ---------------------------------------------------------------------------
__global__ void __launch_bounds__(256, 7) dfe_fused(
    const float* __restrict__ x,
    const float* __restrict__ W1, const float* __restrict__ b1,
    const float* __restrict__ W2, const float* __restrict__ b2,
    float* __restrict__ out)
{
    __shared__ h4     stab[2 * TAB_S];     // persistent: fp16 segment tables
    __shared__ float  sthr[2 * THR_S];     // persistent: sorted thresholds
    __shared__ float2 sxch[8][2][32];      // persistent: per-warp exchange
    // prologue-only:
    __shared__ float sw[2][HN], sb[2][HN], tv_[2][HN], st[2][HN];
    __shared__ int   sidx[2][HN];
    __shared__ float sv[2][EN * HN];

    int tid = threadIdx.x;
    int pairq = blockIdx.x;                // f = pairq*2 + ff
    int bbase = blockIdx.y * ROWS_PER_BLOCK;

    // ================= PROLOGUE: build tables for 2 features =================
    {
        int ffp = tid >> 7;                // prologue feature (0-1)
        int t   = tid & 127;
        int f   = pairq * 2 + ffp;

        // stage W2 row (4KB/feature) with float4 loads
        {
            const float4* src = (const float4*)(W2 + (size_t)f * EN * HN);
            float4* dst = (float4*)sv[ffp];
            #pragma unroll
            for (int r = 0; r < 2; r++) dst[r * 128 + t] = src[r * 128 + t];
        }

        if (t < HN) {
            float w = W1[f * HN + t];
            float b = b1[f * HN + t];
            sw[ffp][t] = w; sb[ffp][t] = b;
            tv_[ffp][t] = (w != 0.0f) ? (-b / w) : 3.0e38f;  // sentinel
        }
        __syncthreads();

        // stable rank-sort of 64 thresholds
        if (t < HN) {
            float tv = tv_[ffp][t];
            int r = 0;
            for (int jj = 0; jj < HN; jj++) {
                float tj = tv_[ffp][jj];
                r += (tj < tv) || (tj == tv && jj < t);
            }
            st[ffp][r] = tv;
            sidx[ffp][r] = t;
        }
        __syncthreads();

        if (t < HN) sthr[ffp * THR_S + t] = st[ffp][t];

        // scan-parallel segment walk: thread = (e, g), g in [0,8)
        {
            int e = t >> 3;
            int g = t & 7;
            const float* w2 = sv[ffp] + e * HN;

            // base (x=-inf active set) partial over h in [g*8, g*8+8)
            float bA = 0.0f, bC = 0.0f;
            #pragma unroll
            for (int k = 0; k < 8; k++) {
                int h = g * 8 + k;
                float w = sw[ffp][h], b = sb[ffp][h], v = w2[h];
                float m = (w < 0.0f) ? 1.0f : 0.0f;
                bA += m * w * v;
                bC += m * b * v;
                bC += (w == 0.0f) ? fmaxf(b, 0.0f) * v : 0.0f;
            }
            #pragma unroll
            for (int d = 1; d < 8; d <<= 1) {
                bA += __shfl_xor_sync(0xffffffffu, bA, d, 8);
                bC += __shfl_xor_sync(0xffffffffu, bC, d, 8);
            }
            float A0 = bA;
            float C0 = bC + b2[f * EN + e];

            // local deltas for s in [g*8, g*8+8): inclusive local prefixes
            float preA[8], preC[8];
            float rA = 0.0f, rC = 0.0f;
            #pragma unroll
            for (int k = 0; k < 8; k++) {
                int s = g * 8 + k;
                int h = sidx[ffp][s];
                float w = sw[ffp][h], b = sb[ffp][h], v = w2[h];
                float sg = (w > 0.0f) ? 1.0f : ((w < 0.0f) ? -1.0f : 0.0f);
                rA += sg * w * v;
                rC += sg * b * v;
                preA[k] = rA; preC[k] = rC;
            }

            // inclusive scan of run totals across the 8-lane subgroup
            float sA = rA, sC = rC;
            #pragma unroll
            for (int d = 1; d < 8; d <<= 1) {
                float tA = __shfl_up_sync(0xffffffffu, sA, d, 8);
                float tC = __shfl_up_sync(0xffffffffu, sC, d, 8);
                if (g >= d) { sA += tA; sC += tC; }
            }
            float exA = sA - rA, exC = sC - rC;

            // write fp16 A/C directly into the smem table (2-byte stores;
            // threads e=2j / e=2j+1 fill adjacent halves of each h4 word)
            int grp = e >> 1, par = e & 1;
            __half* dsth = (__half*)&stab[ffp * TAB_S];
            #pragma unroll
            for (int k = 0; k < 8; k++) {
                int s = g * 8 + k;
                float A = A0 + exA + (k ? preA[k - 1] : 0.0f);
                float C = C0 + exC + (k ? preC[k - 1] : 0.0f);
                dsth[(s * 8 + grp) * 4 + par]     = __float2half_rn(A);
                dsth[(s * 8 + grp) * 4 + 2 + par] = __float2half_rn(C);
            }
            if (g == 7) {   // s = 64
                dsth[(64 * 8 + grp) * 4 + par]     = __float2half_rn(A0 + exA + preA[7]);
                dsth[(64 * 8 + grp) * 4 + 2 + par] = __float2half_rn(C0 + exC + preC[7]);
            }
        }
    }
    __syncthreads();

    // ================= MAIN LOOP: R13 exact =================
    int lane = tid & 31, w = tid >> 5;
    int rrow = lane & 15;           // phase-1 row within 16-row batch
    int ff   = lane >> 4;           // phase-1 feature (0-1)
    int r01  = lane >> 4;           // phase-2 row parity (0-1)
    int ff2  = (lane >> 3) & 1;     // phase-2 feature
    int j    = lane & 7;            // phase-2 e-pair

    const float* thrp = sthr + ff * THR_S;
    const h4*    tabf = stab + ff2 * TAB_S;

    int rb0 = bbase + w * (ROWS_PER_BLOCK / 8);
    const float* xpb  = x   + (size_t)rb0 * FN + pairq * 2 + ff;
    float*       outb = out + (size_t)rb0 * (FN * EN) + pairq * 32 + ff2 * 16 + j * 2;

    float xs = __ldg(xpb + (size_t)rrow * FN);
    int   seg = seg_search(thrp, xs);

    #pragma unroll
    for (int batch = 0; batch < BATCHES; batch++) {
        float2* xch = sxch[w][batch & 1];
        xch[lane] = make_float2(xs, __int_as_float(seg));
        __syncwarp();
        if (batch < BATCHES - 1)
            xs = __ldg(xpb + (size_t)((batch + 1) * 16 + rrow) * FN);

        float* orow = outb + (size_t)(batch * 16) * (FN * EN);
        #pragma unroll
        for (int p = 0; p < 8; p++) {
            int row = p * 2 + r01;
            float2 e = xch[ff2 * 16 + row];   // broadcast across 8 j lanes
            int sg = __float_as_int(e.y);
            h4 v = tabf[sg * 8 + j];
            float2 a = __half22float2(v.a);
            float2 c = __half22float2(v.c);
            float2 o;
            o.x = fmaf(a.x, e.x, c.x);
            o.y = fmaf(a.y, e.x, c.y);
            __stcs((float2*)(orow + (size_t)row * (FN * EN)), o);
        }

        if (batch < BATCHES - 1) seg = seg_search(thrp, xs);
        // no trailing syncwarp: next batch writes the OTHER buffer; this one
        // is rewritten 2 batches later, past the next syncwarp.
    }
}

extern "C" void kernel_launch(void* const* d_in, const int* in_sizes, int n_in,
                              void* d_out, int out_size)
{
    const float* x  = (const float*)d_in[0];
    const float* W1 = (const float*)d_in[1];
    const float* b1 = (const float*)d_in[2];
    const float* W2 = (const float*)d_in[3];
    const float* b2 = (const float*)d_in[4];
    float* out = (float*)d_out;

    dfe_fused<<<dim3(FN / 2, BN / ROWS_PER_BLOCK), 256>>>(x, W1, b1, W2, b2, out);
}

// round 17
// speedup vs baseline: 1.2636x; 1.2636x over previous
#include <cuda_runtime.h>
#include <cuda_bf16.h>
#include <cuda_fp16.h>

// emb[b,f,e] = b2[f,e] + sum_h W2[f,e,h]*relu(x[b,f]*W1[f,h]+b1[f,h])
// Piecewise-linear-in-x: per f, 65 segments; emb = A(seg)*x + C(seg).
// R17 = R15 + x transposed to xT[f][b] (kills 128MB of L2->L1 x re-fetch and
// 16 wf/batch of strided x gather). Transpose folded into launch 1.

#define BN 16384
#define FN 128
#define HN 64
#define EN 16
#define THR_S 72        // threshold stride
#define TAB_S 524       // smem table stride in h4 units
#define ROWS_PER_BLOCK 512
#define BATCHES 4       // per warp: 64 rows = 4 batches of 16

struct __align__(8) h4 { __half2 a, c; };

__device__ h4    g_tab_h[FN * 520];   // per f: 65 segs * 8 h4
__device__ float g_thr[FN * 64];      // sorted hinge thresholds per f
__device__ float g_xT[FN * BN];       // transposed x: [f][b]  (8MB)

// ---------------------------------------------------------------------------
// Kernel 1: precompute (grid.y==0) + x transpose (grid.y in 1..4).
// Precompute: one block per f, 128 threads, scan-parallel walk (R14 exact).
// Transpose: block = 128 rows x 32 features tile; coalesced both directions.
// ---------------------------------------------------------------------------
__global__ void __launch_bounds__(128) dfe_pre(
    const float* __restrict__ x,
    const float* __restrict__ W1, const float* __restrict__ b1,
    const float* __restrict__ W2, const float* __restrict__ b2)
{
    int tid = threadIdx.x;

    if (blockIdx.y > 0) {
        // ---------------- transpose tile: 128 rows x 32 features ----------------
        __shared__ float tile[32][132];
        int fq = blockIdx.y - 1;           // feature quad of 32: f in [fq*32, fq*32+32)
        int rb = blockIdx.x;               // row block: b in [rb*128, rb*128+128)
        const float* src = x + (size_t)(rb * 128) * FN + fq * 32;

        #pragma unroll
        for (int k = 0; k < 8; k++) {
            int i = k * 128 + tid;          // 1024 float4s
            int row = i >> 3, c4 = i & 7;
            float4 v = *(const float4*)(src + (size_t)row * FN + c4 * 4);
            tile[c4 * 4 + 0][row] = v.x;
            tile[c4 * 4 + 1][row] = v.y;
            tile[c4 * 4 + 2][row] = v.z;
            tile[c4 * 4 + 3][row] = v.w;
        }
        __syncthreads();
        #pragma unroll
        for (int c = 0; c < 32; c++)
            g_xT[(size_t)(fq * 32 + c) * BN + rb * 128 + tid] = tile[c][tid];
        return;
    }

    // ---------------- precompute: feature f = blockIdx.x ----------------
    int f = blockIdx.x;

    __shared__ float sw[HN], sb[HN], tv_[HN], st[HN];
    __shared__ int   sidx[HN];
    __shared__ float sv[EN * HN];
    __shared__ float stab[65 * 32];

    {
        const float4* src = (const float4*)(W2 + (size_t)f * EN * HN);
        float4* dst = (float4*)sv;
        #pragma unroll
        for (int r = 0; r < 2; r++) dst[r * 128 + tid] = src[r * 128 + tid];
    }

    if (tid < HN) {
        float w = W1[f * HN + tid];
        float b = b1[f * HN + tid];
        sw[tid] = w; sb[tid] = b;
        tv_[tid] = (w != 0.0f) ? (-b / w) : 3.0e38f;  // sentinel: never crossed
    }
    __syncthreads();

    // stable rank-sort of 64 thresholds
    if (tid < HN) {
        float tv = tv_[tid];
        int r = 0;
        for (int j = 0; j < HN; j++) {
            float tj = tv_[j];
            r += (tj < tv) || (tj == tv && j < tid);
        }
        st[r] = tv;
        sidx[r] = tid;
    }
    __syncthreads();

    if (tid < HN) g_thr[f * HN + tid] = st[tid];

    // parallel segment walk: thread = (e, g), g in [0,8)
    {
        int e = tid >> 3;
        int g = tid & 7;
        const float* w2 = sv + e * HN;

        float bA = 0.0f, bC = 0.0f;
        #pragma unroll
        for (int k = 0; k < 8; k++) {
            int h = g * 8 + k;
            float w = sw[h], b = sb[h], v = w2[h];
            float m = (w < 0.0f) ? 1.0f : 0.0f;
            bA += m * w * v;
            bC += m * b * v;
            bC += (w == 0.0f) ? fmaxf(b, 0.0f) * v : 0.0f;
        }
        #pragma unroll
        for (int d = 1; d < 8; d <<= 1) {
            bA += __shfl_xor_sync(0xffffffffu, bA, d, 8);
            bC += __shfl_xor_sync(0xffffffffu, bC, d, 8);
        }
        float A0 = bA;
        float C0 = bC + b2[f * EN + e];

        float preA[8], preC[8];
        float rA = 0.0f, rC = 0.0f;
        #pragma unroll
        for (int k = 0; k < 8; k++) {
            int s = g * 8 + k;
            int h = sidx[s];
            float w = sw[h], b = sb[h], v = w2[h];
            float sg = (w > 0.0f) ? 1.0f : ((w < 0.0f) ? -1.0f : 0.0f);
            rA += sg * w * v;
            rC += sg * b * v;
            preA[k] = rA; preC[k] = rC;
        }

        float sA = rA, sC = rC;
        #pragma unroll
        for (int d = 1; d < 8; d <<= 1) {
            float tA = __shfl_up_sync(0xffffffffu, sA, d, 8);
            float tC = __shfl_up_sync(0xffffffffu, sC, d, 8);
            if (g >= d) { sA += tA; sC += tC; }
        }
        float exA = sA - rA, exC = sC - rC;

        int grp = e >> 1, par = e & 1;
        #pragma unroll
        for (int k = 0; k < 8; k++) {
            int s = g * 8 + k;
            float A = A0 + exA + (k ? preA[k - 1] : 0.0f);
            float C = C0 + exC + (k ? preC[k - 1] : 0.0f);
            stab[s * 32 + grp * 4 + par]     = A;
            stab[s * 32 + grp * 4 + 2 + par] = C;
        }
        if (g == 7) {
            stab[64 * 32 + grp * 4 + par]     = A0 + exA + preA[7];
            stab[64 * 32 + grp * 4 + 2 + par] = C0 + exC + preC[7];
        }
    }
    __syncthreads();

    // pack fp32 staging -> fp16 table, coalesced writeback
    for (int i = tid; i < 520; i += 128) {
        int s = i >> 3, j = i & 7;
        const float* p = stab + s * 32 + j * 4;
        h4 v;
        v.a = __floats2half2_rn(p[0], p[1]);
        v.c = __floats2half2_rn(p[2], p[3]);
        g_tab_h[f * 520 + i] = v;
    }
}

// ---------------------------------------------------------------------------
// Branch-free count of { thr[t] <= xs } over 64 sorted entries (7 LDS).
// ---------------------------------------------------------------------------
__device__ __forceinline__ int seg_search(const float* __restrict__ thrp, float xs)
{
    int p = (thrp[31] <= xs) ? 32 : 0;
    p += (thrp[p + 15] <= xs) ? 16 : 0;
    p += (thrp[p + 7]  <= xs) ? 8  : 0;
    p += (thrp[p + 3]  <= xs) ? 4  : 0;
    p += (thrp[p + 1]  <= xs) ? 2  : 0;
    p += (thrp[p]      <= xs) ? 1  : 0;
    return p + ((thrp[p] <= xs) ? 1 : 0);   // in [0,64]
}

// ---------------------------------------------------------------------------
// Kernel 2: evaluation — R15 exact except x comes from g_xT (contiguous per
// feature: the per-batch x LDG touches 2 lines instead of 16).
// Block = 2 features x 512 rows, 256 threads; grid (64,32)=2048 blocks.
// ---------------------------------------------------------------------------
__global__ void __launch_bounds__(256, 8) dfe_eval(float* __restrict__ out)
{
    __shared__ h4     stab[2 * TAB_S];
    __shared__ float  sthr[2 * THR_S];
    __shared__ float2 sxch[8][2][32];    // per-warp double-buffered exchange

    int tid = threadIdx.x;
    int pairq = blockIdx.x;              // feature pair index: f = pairq*2 + ff
    int bbase = blockIdx.y * ROWS_PER_BLOCK;

    #pragma unroll
    for (int ff = 0; ff < 2; ff++)
        for (int i = tid; i < 520; i += 256)
            stab[ff * TAB_S + i] = g_tab_h[(pairq * 2 + ff) * 520 + i];
    for (int i = tid; i < 2 * 64; i += 256)
        sthr[(i >> 6) * THR_S + (i & 63)] = g_thr[pairq * 128 + i];
    __syncthreads();

    int lane = tid & 31, w = tid >> 5;
    int rrow = lane & 15;           // phase-1 row within 16-row batch
    int ff   = lane >> 4;           // phase-1 feature (0-1)
    int r01  = lane >> 4;           // phase-2 row parity (0-1)
    int ff2  = (lane >> 3) & 1;     // phase-2 feature
    int j    = lane & 7;            // phase-2 e-pair

    const float* thrp = sthr + ff * THR_S;
    const h4*    tabf = stab + ff2 * TAB_S;

    int rb0 = bbase + w * (ROWS_PER_BLOCK / 8);
    const float* xpb  = g_xT + (size_t)(pairq * 2 + ff) * BN + rb0;   // contiguous rows
    float*       outb = out + (size_t)rb0 * (FN * EN) + pairq * 32 + ff2 * 16 + j * 2;

    float xs = __ldg(xpb + rrow);
    int   seg = seg_search(thrp, xs);

    #pragma unroll
    for (int batch = 0; batch < BATCHES; batch++) {
        float2* xch = sxch[w][batch & 1];
        xch[lane] = make_float2(xs, __int_as_float(seg));
        __syncwarp();
        if (batch < BATCHES - 1)
            xs = __ldg(xpb + (batch + 1) * 16 + rrow);

        float* orow = outb + (size_t)(batch * 16) * (FN * EN);
        #pragma unroll
        for (int p = 0; p < 8; p++) {
            int row = p * 2 + r01;
            float2 e = xch[ff2 * 16 + row];   // broadcast across 8 j lanes
            int sg = __float_as_int(e.y);
            h4 v = tabf[sg * 8 + j];
            float2 a = __half22float2(v.a);
            float2 c = __half22float2(v.c);
            float2 o;
            o.x = fmaf(a.x, e.x, c.x);
            o.y = fmaf(a.y, e.x, c.y);
            __stcs((float2*)(orow + (size_t)row * (FN * EN)), o);
        }

        if (batch < BATCHES - 1) seg = seg_search(thrp, xs);
        // no trailing syncwarp: next batch writes the OTHER buffer; this one
        // is rewritten 2 batches later, past the next syncwarp.
    }
}

extern "C" void kernel_launch(void* const* d_in, const int* in_sizes, int n_in,
                              void* d_out, int out_size)
{
    const float* x  = (const float*)d_in[0];
    const float* W1 = (const float*)d_in[1];
    const float* b1 = (const float*)d_in[2];
    const float* W2 = (const float*)d_in[3];
    const float* b2 = (const float*)d_in[4];
    float* out = (float*)d_out;

    dfe_pre<<<dim3(FN, 5), 128>>>(x, W1, b1, W2, b2);   // y=0: tables, y=1..4: transpose
    dfe_eval<<<dim3(FN / 2, BN / ROWS_PER_BLOCK), 256>>>(out);
}